// round 4
// baseline (speedup 1.0000x reference)
#include <cuda_runtime.h>
#include <math.h>

// Problem constants
#define BDIM 16
#define CDIM 512
#define NDIM 1024
#define NHEADS 8
#define DHEAD 64
// scale = DHEAD^-0.5
#define QSCALE 0.125f

// Scratch: q (pre-scaled), k' (= k + cp_tab), v. Layout [B][C][N] fp32.
// 3 x 33.5 MB device globals (allocation-free scratch).
__device__ float g_q[BDIM * CDIM * NDIM];
__device__ float g_k[BDIM * CDIM * NDIM];
__device__ float g_v[BDIM * CDIM * NDIM];

// ---------------------------------------------------------------------------
// Kernel 1: fused QKV projection.
//   out[o][n] = sum_c W[o][c] * x[b][c][n] + bias[o]   (per batch b)
// Epilogue: mat 0 (q): *= QSCALE
//           mat 1 (k): += rel_h[dd][n/32] + rel_w[dd][n%32]  (dd = o % 64)
// Tile: 64 (o) x 128 (n) x 16 (k). 256 threads, each 4x8.
// ---------------------------------------------------------------------------
__global__ __launch_bounds__(256) void qkv_gemm_kernel(
    const float* __restrict__ x,
    const float* __restrict__ Wq, const float* __restrict__ bq,
    const float* __restrict__ Wk, const float* __restrict__ bk,
    const float* __restrict__ Wv, const float* __restrict__ bv,
    const float* __restrict__ rel_h, const float* __restrict__ rel_w)
{
    const int mat = blockIdx.z >> 4;   // 0=q, 1=k, 2=v
    const int b   = blockIdx.z & 15;

    const float* __restrict__ W    = (mat == 0) ? Wq : (mat == 1) ? Wk : Wv;
    const float* __restrict__ bias = (mat == 0) ? bq : (mat == 1) ? bk : bv;
    float* __restrict__ out        = (mat == 0) ? g_q : (mat == 1) ? g_k : g_v;

    const int o0 = blockIdx.y * 64;
    const int n0 = blockIdx.x * 128;

    __shared__ float Ws[16][68];    // [c][o], padded
    __shared__ float Xs[16][128];   // [c][n]

    const int tid  = threadIdx.x;
    const int trow = tid >> 4;      // 0..15 -> o (x4)
    const int tcol = tid & 15;      // 0..15 -> n (x8)

    float acc[4][8];
#pragma unroll
    for (int r = 0; r < 4; r++)
#pragma unroll
        for (int s = 0; s < 8; s++) acc[r][s] = 0.f;

    const float* __restrict__ xb = x + (size_t)b * CDIM * NDIM;

    const int wr = tid >> 2;          // 0..63 (o row of W tile)
    const int wc = (tid & 3) << 2;    // 0,4,8,12 (c offset)
    const int xr = tid >> 4;          // 0..15 (c row of X tile)
    const int xc = (tid & 15) << 3;   // 0..120 (n offset)

    for (int k0 = 0; k0 < CDIM; k0 += 16) {
        // Load W tile (64x16) transposed into Ws[c][o]
        float4 w4 = *(const float4*)&W[(size_t)(o0 + wr) * CDIM + k0 + wc];
        // Load X tile (16x128) into Xs[c][n]
        float4 xa = *(const float4*)&xb[(size_t)(k0 + xr) * NDIM + n0 + xc];
        float4 xc4 = *(const float4*)&xb[(size_t)(k0 + xr) * NDIM + n0 + xc + 4];
        Ws[wc + 0][wr] = w4.x;
        Ws[wc + 1][wr] = w4.y;
        Ws[wc + 2][wr] = w4.z;
        Ws[wc + 3][wr] = w4.w;
        *(float4*)&Xs[xr][xc]     = xa;
        *(float4*)&Xs[xr][xc + 4] = xc4;
        __syncthreads();

#pragma unroll
        for (int kk = 0; kk < 16; kk++) {
            float4 a4 = *(const float4*)&Ws[kk][trow << 2];
            float4 b0 = *(const float4*)&Xs[kk][tcol << 3];
            float4 b1 = *(const float4*)&Xs[kk][(tcol << 3) + 4];
            float a[4] = {a4.x, a4.y, a4.z, a4.w};
            float bb[8] = {b0.x, b0.y, b0.z, b0.w, b1.x, b1.y, b1.z, b1.w};
#pragma unroll
            for (int r = 0; r < 4; r++)
#pragma unroll
                for (int s = 0; s < 8; s++)
                    acc[r][s] += a[r] * bb[s];
        }
        __syncthreads();
    }

    // Epilogue
    const size_t obase = (size_t)b * CDIM * NDIM;
#pragma unroll
    for (int r = 0; r < 4; r++) {
        const int o  = o0 + (trow << 2) + r;
        const float bi = bias[o];
        const int dd = o & 63;
#pragma unroll
        for (int s = 0; s < 8; s++) {
            const int n = n0 + (tcol << 3) + s;
            float val = acc[r][s] + bi;
            if (mat == 0) {
                val *= QSCALE;
            } else if (mat == 1) {
                // cp_tab[dd][n] = rel_h[dd][n>>5] + rel_w[dd][n&31]
                val += rel_h[dd * 32 + (n >> 5)] + rel_w[dd * 32 + (n & 31)];
            }
            out[obase + (size_t)o * NDIM + n] = val;
        }
    }
}

// ---------------------------------------------------------------------------
// Kernel 2: flash attention per (b,h).
//   q', k', v: [d=64][N=1024] per (b,h).  out[b,h,i,dd] = softmax(q'^T k')_i . v
// Block: 128 threads, 64 queries (one i-tile). KV tiles of 32.
// S tile 64x32: thread grid 16(i-rows x4) x 8(j-cols x4).
// O tile 64x64: same trow, dd = (tid&7)*8 .. +7.
// ---------------------------------------------------------------------------
__global__ __launch_bounds__(128) void attn_kernel(float* __restrict__ out)
{
    const int bh = blockIdx.y;            // 0..127  (b*8 + h)
    const int i0 = blockIdx.x * 64;

    const float* __restrict__ qp = g_q + (size_t)bh * DHEAD * NDIM;
    const float* __restrict__ kp = g_k + (size_t)bh * DHEAD * NDIM;
    const float* __restrict__ vp = g_v + (size_t)bh * DHEAD * NDIM;

    __shared__ float Qs[64][64];   // [d][i]
    __shared__ float KP[64][36];   // K tile [d][j], reused as P tile [i][j]
    __shared__ float Vs[32][65];   // V tile transposed [j][dd], odd stride

    const int tid  = threadIdx.x;
    const int tcol = tid & 7;
    const int trow = tid >> 3;     // 0..15
    const int ib   = trow << 2;    // query row base (x4)
    const int jb   = tcol << 2;    // S col base   (x4)
    const int db   = tcol << 3;    // O col base   (x8)

    // Load Q tile [d=0..63][i0..i0+63]
    for (int t = tid; t < 64 * 16; t += 128) {
        const int row = t >> 4;
        const int c4  = (t & 15) << 2;
        *(float4*)&Qs[row][c4] = *(const float4*)&qp[(size_t)row * NDIM + i0 + c4];
    }

    float m[4], l[4], o[4][8];
#pragma unroll
    for (int r = 0; r < 4; r++) {
        m[r] = -INFINITY;
        l[r] = 0.f;
#pragma unroll
        for (int c = 0; c < 8; c++) o[r][c] = 0.f;
    }
    __syncthreads();

    for (int jt = 0; jt < NDIM / 32; jt++) {
        const int j0 = jt * 32;

        // Load K tile [d][j] (64x32)
        for (int t = tid; t < 64 * 8; t += 128) {
            const int row = t >> 3;
            const int c4  = (t & 7) << 2;
            *(float4*)&KP[row][c4] = *(const float4*)&kp[(size_t)row * NDIM + j0 + c4];
        }
        __syncthreads();

        // S = Q^T K  (4x4 per thread)
        float s[4][4];
#pragma unroll
        for (int r = 0; r < 4; r++)
#pragma unroll
            for (int c = 0; c < 4; c++) s[r][c] = 0.f;

#pragma unroll 16
        for (int d = 0; d < 64; d++) {
            float4 a4 = *(const float4*)&Qs[d][ib];
            float4 k4 = *(const float4*)&KP[d][jb];
            float a[4] = {a4.x, a4.y, a4.z, a4.w};
            float kk[4] = {k4.x, k4.y, k4.z, k4.w};
#pragma unroll
            for (int r = 0; r < 4; r++)
#pragma unroll
                for (int c = 0; c < 4; c++)
                    s[r][c] += a[r] * kk[c];
        }
        __syncthreads();   // everyone done reading KP as K

        // Online softmax (row reduce over the 8-lane group sharing a row)
#pragma unroll
        for (int r = 0; r < 4; r++) {
            float mt = fmaxf(fmaxf(s[r][0], s[r][1]), fmaxf(s[r][2], s[r][3]));
            mt = fmaxf(mt, __shfl_xor_sync(0xffffffffu, mt, 1));
            mt = fmaxf(mt, __shfl_xor_sync(0xffffffffu, mt, 2));
            mt = fmaxf(mt, __shfl_xor_sync(0xffffffffu, mt, 4));
            const float mn = fmaxf(m[r], mt);
            const float alpha = __expf(m[r] - mn);
            m[r] = mn;
            float rs = 0.f;
#pragma unroll
            for (int c = 0; c < 4; c++) {
                s[r][c] = __expf(s[r][c] - mn);
                rs += s[r][c];
            }
            rs += __shfl_xor_sync(0xffffffffu, rs, 1);
            rs += __shfl_xor_sync(0xffffffffu, rs, 2);
            rs += __shfl_xor_sync(0xffffffffu, rs, 4);
            l[r] = l[r] * alpha + rs;
#pragma unroll
            for (int c = 0; c < 8; c++) o[r][c] *= alpha;
        }

        // Write P over the K buffer; concurrently load V transposed
#pragma unroll
        for (int r = 0; r < 4; r++)
            *(float4*)&KP[ib + r][jb] = make_float4(s[r][0], s[r][1], s[r][2], s[r][3]);

        for (int t = tid; t < 64 * 32; t += 128) {
            const int dd = t >> 5;
            const int j  = t & 31;
            Vs[j][dd] = vp[(size_t)dd * NDIM + j0 + j];
        }
        __syncthreads();

        // O += P V^T   (4x8 per thread)
#pragma unroll 4
        for (int j = 0; j < 32; j++) {
            const float pr0 = KP[ib + 0][j];
            const float pr1 = KP[ib + 1][j];
            const float pr2 = KP[ib + 2][j];
            const float pr3 = KP[ib + 3][j];
#pragma unroll
            for (int c = 0; c < 8; c++) {
                const float vv = Vs[j][db + c];
                o[0][c] += pr0 * vv;
                o[1][c] += pr1 * vv;
                o[2][c] += pr2 * vv;
                o[3][c] += pr3 * vv;
            }
        }
        __syncthreads();   // before overwriting KP with next K tile
    }

    // Epilogue: out[((bh)*N + i)*64 + dd] = o / l
    float* __restrict__ outp = out + (size_t)bh * NDIM * DHEAD;
#pragma unroll
    for (int r = 0; r < 4; r++) {
        const float inv = 1.0f / l[r];
        const int i = i0 + ib + r;
        float4 v0 = make_float4(o[r][0] * inv, o[r][1] * inv, o[r][2] * inv, o[r][3] * inv);
        float4 v1 = make_float4(o[r][4] * inv, o[r][5] * inv, o[r][6] * inv, o[r][7] * inv);
        *(float4*)&outp[(size_t)i * DHEAD + db]     = v0;
        *(float4*)&outp[(size_t)i * DHEAD + db + 4] = v1;
    }
}

// ---------------------------------------------------------------------------
extern "C" void kernel_launch(void* const* d_in, const int* in_sizes, int n_in,
                              void* d_out, int out_size)
{
    const float* x     = (const float*)d_in[0];
    const float* Wq    = (const float*)d_in[1];
    const float* bq    = (const float*)d_in[2];
    const float* Wk    = (const float*)d_in[3];
    const float* bk    = (const float*)d_in[4];
    const float* Wv    = (const float*)d_in[5];
    const float* bv    = (const float*)d_in[6];
    const float* rel_h = (const float*)d_in[7];
    const float* rel_w = (const float*)d_in[8];
    float* out = (float*)d_out;

    // QKV projections + cp_tab fold into k
    dim3 g1(NDIM / 128, CDIM / 64, 3 * BDIM);
    qkv_gemm_kernel<<<g1, 256>>>(x, Wq, bq, Wk, bk, Wv, bv, rel_h, rel_w);

    // Flash attention
    dim3 g2(NDIM / 64, BDIM * NHEADS);
    attn_kernel<<<g2, 128>>>(out);
}

// round 7
// speedup vs baseline: 1.3780x; 1.3780x over previous
#include <cuda_runtime.h>
#include <math.h>

// Problem constants
#define BDIM 16
#define CDIM 512
#define NDIM 1024
#define NHEADS 8
#define DHEAD 64
#define QSCALE 0.125f

// Scratch: q (pre-scaled), k' (= k + cp_tab), v. Layout [B][C][N] fp32.
__device__ float g_q[BDIM * CDIM * NDIM];
__device__ float g_k[BDIM * CDIM * NDIM];
__device__ float g_v[BDIM * CDIM * NDIM];

// ---------------------------------------------------------------------------
// Kernel 1: fused QKV projection, 128(o) x 128(n) tile, 256 threads, 8x8/thread.
//   out[o][n] = sum_c W[o][c] * x[b][c][n] + bias[o]
// Epilogue: mat0 (q): *= QSCALE; mat1 (k): += rel_h + rel_w table.
// Operand groups split (4t..4t+3) U (64+4t..) for conflict-free LDS.128.
// ---------------------------------------------------------------------------
__global__ __launch_bounds__(256) void qkv_gemm_kernel(
    const float* __restrict__ x,
    const float* __restrict__ Wq, const float* __restrict__ bq,
    const float* __restrict__ Wk, const float* __restrict__ bk,
    const float* __restrict__ Wv, const float* __restrict__ bv,
    const float* __restrict__ rel_h, const float* __restrict__ rel_w)
{
    const int mat = blockIdx.z >> 4;   // 0=q, 1=k, 2=v
    const int b   = blockIdx.z & 15;

    const float* __restrict__ W    = (mat == 0) ? Wq : (mat == 1) ? Wk : Wv;
    const float* __restrict__ bias = (mat == 0) ? bq : (mat == 1) ? bk : bv;
    float* __restrict__ out        = (mat == 0) ? g_q : (mat == 1) ? g_k : g_v;

    const int o0 = blockIdx.y * 128;
    const int n0 = blockIdx.x * 128;

    __shared__ float Ws[16 * 132];   // [k][o] transposed, padded
    __shared__ float Xs[16 * 132];   // [k][n], padded

    const int tid = threadIdx.x;
    const int tr  = tid >> 4;        // 0..15 -> o groups
    const int tc  = tid & 15;        // 0..15 -> n groups

    float acc[8][8];
#pragma unroll
    for (int r = 0; r < 8; r++)
#pragma unroll
        for (int c = 0; c < 8; c++) acc[r][c] = 0.f;

    const float* __restrict__ xb = x + (size_t)b * CDIM * NDIM;

    // gmem load assignments
    const int wrow = tid >> 1;            // 0..127 (o row)
    const int wk   = (tid & 1) * 8;       // 0 or 8 (k offset)
    const int xrow = tid >> 4;            // 0..15  (k row)
    const int xcol = (tid & 15) * 8;      // n offset

    // Prefetch first k-tile into registers
    float4 w0 = *(const float4*)&W[(size_t)(o0 + wrow) * CDIM + wk];
    float4 w1 = *(const float4*)&W[(size_t)(o0 + wrow) * CDIM + wk + 4];
    float4 x0 = *(const float4*)&xb[(size_t)xrow * NDIM + n0 + xcol];
    float4 x1 = *(const float4*)&xb[(size_t)xrow * NDIM + n0 + xcol + 4];

    for (int k0 = 0; k0 < CDIM; k0 += 16) {
        __syncthreads();   // prior tile's compute done
        // Store staged regs to smem (W transposed)
        Ws[(wk + 0) * 132 + wrow] = w0.x;
        Ws[(wk + 1) * 132 + wrow] = w0.y;
        Ws[(wk + 2) * 132 + wrow] = w0.z;
        Ws[(wk + 3) * 132 + wrow] = w0.w;
        Ws[(wk + 4) * 132 + wrow] = w1.x;
        Ws[(wk + 5) * 132 + wrow] = w1.y;
        Ws[(wk + 6) * 132 + wrow] = w1.z;
        Ws[(wk + 7) * 132 + wrow] = w1.w;
        *(float4*)&Xs[xrow * 132 + xcol]     = x0;
        *(float4*)&Xs[xrow * 132 + xcol + 4] = x1;
        __syncthreads();

        // Prefetch next tile (LDG issues before the FMA block)
        if (k0 + 16 < CDIM) {
            w0 = *(const float4*)&W[(size_t)(o0 + wrow) * CDIM + k0 + 16 + wk];
            w1 = *(const float4*)&W[(size_t)(o0 + wrow) * CDIM + k0 + 16 + wk + 4];
            x0 = *(const float4*)&xb[(size_t)(k0 + 16 + xrow) * NDIM + n0 + xcol];
            x1 = *(const float4*)&xb[(size_t)(k0 + 16 + xrow) * NDIM + n0 + xcol + 4];
        }

#pragma unroll 8
        for (int kk = 0; kk < 16; kk++) {
            float4 a0 = *(const float4*)&Ws[kk * 132 + 4 * tr];
            float4 a1 = *(const float4*)&Ws[kk * 132 + 64 + 4 * tr];
            float4 b0 = *(const float4*)&Xs[kk * 132 + 4 * tc];
            float4 b1 = *(const float4*)&Xs[kk * 132 + 64 + 4 * tc];
            float a[8] = {a0.x, a0.y, a0.z, a0.w, a1.x, a1.y, a1.z, a1.w};
            float bb[8] = {b0.x, b0.y, b0.z, b0.w, b1.x, b1.y, b1.z, b1.w};
#pragma unroll
            for (int r = 0; r < 8; r++)
#pragma unroll
                for (int c = 0; c < 8; c++)
                    acc[r][c] += a[r] * bb[c];
        }
    }

    // Epilogue
    const size_t obase = (size_t)b * CDIM * NDIM;
#pragma unroll
    for (int r = 0; r < 8; r++) {
        const int o  = o0 + ((r < 4) ? (4 * tr + r) : (64 + 4 * tr + (r - 4)));
        const float bi = bias[o];
        const int dd = o & 63;
#pragma unroll
        for (int g = 0; g < 2; g++) {
            const int nb = n0 + (g ? (64 + 4 * tc) : (4 * tc));
            float vals[4];
#pragma unroll
            for (int c = 0; c < 4; c++) {
                const int n = nb + c;
                float val = acc[r][g * 4 + c] + bi;
                if (mat == 0) {
                    val *= QSCALE;
                } else if (mat == 1) {
                    val += rel_h[dd * 32 + (n >> 5)] + rel_w[dd * 32 + (n & 31)];
                }
                vals[c] = val;
            }
            *(float4*)&out[obase + (size_t)o * NDIM + nb] =
                make_float4(vals[0], vals[1], vals[2], vals[3]);
        }
    }
}

// ---------------------------------------------------------------------------
// Kernel 2: flash attention. Ti=128 queries, Tj=64 keys, 128 threads (16x8).
// Per-thread 8x8 S fragment and 8x8 O fragment (1.0 B smem per FMA).
// P goes through smem transposed: PT[j][i] so PV is pure LDS.128.
// Dynamic smem: Qs 64x132 | Ks 64x68 | PT 64x132 | Vs 64x68 = 100 KB.
// ---------------------------------------------------------------------------
__global__ __launch_bounds__(128) void attn_kernel(float* __restrict__ out)
{
    extern __shared__ float sm[];
    float* Qs = sm;                 // [d=64][i=128], stride 132
    float* Ks = sm + 8448;          // [d=64][j=64],  stride 68
    float* PT = sm + 12800;         // [j=64][i=128], stride 132
    float* Vs = sm + 21248;         // [j=64][dd=64], stride 68

    const int bh = blockIdx.y;
    const int i0 = blockIdx.x * 128;

    const float* __restrict__ qp = g_q + (size_t)bh * DHEAD * NDIM;
    const float* __restrict__ kp = g_k + (size_t)bh * DHEAD * NDIM;
    const float* __restrict__ vp = g_v + (size_t)bh * DHEAD * NDIM;

    const int tid = threadIdx.x;
    const int tc  = tid & 7;        // 0..7  (j / dd groups)
    const int tr  = tid >> 3;       // 0..15 (i groups)

    // Load Q tile [d][i0..i0+127]
    for (int t = tid; t < 64 * 32; t += 128) {
        const int d  = t >> 5;
        const int i4 = (t & 31) * 4;
        *(float4*)&Qs[d * 132 + i4] = *(const float4*)&qp[(size_t)d * NDIM + i0 + i4];
    }

    float m[8], l[8], o[8][8];
#pragma unroll
    for (int r = 0; r < 8; r++) {
        m[r] = -INFINITY;
        l[r] = 0.f;
#pragma unroll
        for (int c = 0; c < 8; c++) o[r][c] = 0.f;
    }

    for (int jt = 0; jt < NDIM / 64; jt++) {
        const int j0 = jt * 64;

        // Load K tile [d][j] (64x64)
        for (int t = tid; t < 64 * 16; t += 128) {
            const int d  = t >> 4;
            const int j4 = (t & 15) * 4;
            *(float4*)&Ks[d * 68 + j4] = *(const float4*)&kp[(size_t)d * NDIM + j0 + j4];
        }
        // Load V tile transposed [j][dd] (64x64)
        for (int t = tid; t < 64 * 64; t += 128) {
            const int dd = t >> 6;
            const int j  = t & 63;
            Vs[j * 68 + dd] = vp[(size_t)dd * NDIM + j0 + j];
        }
        __syncthreads();   // K, V (and Q on first iter) ready

        // S = Q^T K  (8x8 per thread)
        float s[8][8];
#pragma unroll
        for (int r = 0; r < 8; r++)
#pragma unroll
            for (int c = 0; c < 8; c++) s[r][c] = 0.f;

#pragma unroll 8
        for (int d = 0; d < 64; d++) {
            float4 qa = *(const float4*)&Qs[d * 132 + 4 * tr];
            float4 qb = *(const float4*)&Qs[d * 132 + 64 + 4 * tr];
            float4 ka = *(const float4*)&Ks[d * 68 + 4 * tc];
            float4 kb = *(const float4*)&Ks[d * 68 + 32 + 4 * tc];
            float a[8] = {qa.x, qa.y, qa.z, qa.w, qb.x, qb.y, qb.z, qb.w};
            float kv[8] = {ka.x, ka.y, ka.z, ka.w, kb.x, kb.y, kb.z, kb.w};
#pragma unroll
            for (int r = 0; r < 8; r++)
#pragma unroll
                for (int c = 0; c < 8; c++)
                    s[r][c] += a[r] * kv[c];
        }

        // Online softmax: reduce over the 8-lane column group
#pragma unroll
        for (int r = 0; r < 8; r++) {
            float mt = s[r][0];
#pragma unroll
            for (int c = 1; c < 8; c++) mt = fmaxf(mt, s[r][c]);
            mt = fmaxf(mt, __shfl_xor_sync(0xffffffffu, mt, 1));
            mt = fmaxf(mt, __shfl_xor_sync(0xffffffffu, mt, 2));
            mt = fmaxf(mt, __shfl_xor_sync(0xffffffffu, mt, 4));
            const float mn = fmaxf(m[r], mt);
            const float alpha = __expf(m[r] - mn);
            m[r] = mn;
            float rs = 0.f;
#pragma unroll
            for (int c = 0; c < 8; c++) {
                s[r][c] = __expf(s[r][c] - mn);
                rs += s[r][c];
            }
            rs += __shfl_xor_sync(0xffffffffu, rs, 1);
            rs += __shfl_xor_sync(0xffffffffu, rs, 2);
            rs += __shfl_xor_sync(0xffffffffu, rs, 4);
            l[r] = l[r] * alpha + rs;
#pragma unroll
            for (int c = 0; c < 8; c++) o[r][c] *= alpha;
        }

        // Write P transposed: PT[j][i] (float4 over the i dimension)
#pragma unroll
        for (int rj = 0; rj < 8; rj++) {
            const int jv = (rj < 4) ? (4 * tc + rj) : (32 + 4 * tc + (rj - 4));
            *(float4*)&PT[jv * 132 + 4 * tr] =
                make_float4(s[0][rj], s[1][rj], s[2][rj], s[3][rj]);
            *(float4*)&PT[jv * 132 + 64 + 4 * tr] =
                make_float4(s[4][rj], s[5][rj], s[6][rj], s[7][rj]);
        }
        __syncthreads();   // PT complete

        // O += P V   (8x8 per thread, all LDS.128)
#pragma unroll 8
        for (int j = 0; j < 64; j++) {
            float4 pa = *(const float4*)&PT[j * 132 + 4 * tr];
            float4 pb = *(const float4*)&PT[j * 132 + 64 + 4 * tr];
            float4 va = *(const float4*)&Vs[j * 68 + 4 * tc];
            float4 vb = *(const float4*)&Vs[j * 68 + 32 + 4 * tc];
            float p[8] = {pa.x, pa.y, pa.z, pa.w, pb.x, pb.y, pb.z, pb.w};
            float vv[8] = {va.x, va.y, va.z, va.w, vb.x, vb.y, vb.z, vb.w};
#pragma unroll
            for (int r = 0; r < 8; r++)
#pragma unroll
                for (int c = 0; c < 8; c++)
                    o[r][c] += p[r] * vv[c];
        }
        __syncthreads();   // PV done; K/V/PT can be overwritten
    }

    // Epilogue: out[bh][i][dd] = o / l
    float* __restrict__ outp = out + (size_t)bh * NDIM * DHEAD;
#pragma unroll
    for (int r = 0; r < 8; r++) {
        const float inv = 1.0f / l[r];
        const int i = i0 + ((r < 4) ? (4 * tr + r) : (64 + 4 * tr + (r - 4)));
        *(float4*)&outp[(size_t)i * DHEAD + 4 * tc] =
            make_float4(o[r][0] * inv, o[r][1] * inv, o[r][2] * inv, o[r][3] * inv);
        *(float4*)&outp[(size_t)i * DHEAD + 32 + 4 * tc] =
            make_float4(o[r][4] * inv, o[r][5] * inv, o[r][6] * inv, o[r][7] * inv);
    }
}

// ---------------------------------------------------------------------------
extern "C" void kernel_launch(void* const* d_in, const int* in_sizes, int n_in,
                              void* d_out, int out_size)
{
    const float* x     = (const float*)d_in[0];
    const float* Wq    = (const float*)d_in[1];
    const float* bq    = (const float*)d_in[2];
    const float* Wk    = (const float*)d_in[3];
    const float* bk    = (const float*)d_in[4];
    const float* Wv    = (const float*)d_in[5];
    const float* bv    = (const float*)d_in[6];
    const float* rel_h = (const float*)d_in[7];
    const float* rel_w = (const float*)d_in[8];
    float* out = (float*)d_out;

    // Attention kernel needs 100 KB dynamic smem
    cudaFuncSetAttribute(attn_kernel,
                         cudaFuncAttributeMaxDynamicSharedMemorySize, 102400);

    // QKV projections + cp_tab fold into k
    dim3 g1(NDIM / 128, CDIM / 128, 3 * BDIM);
    qkv_gemm_kernel<<<g1, 256>>>(x, Wq, bq, Wk, bk, Wv, bv, rel_h, rel_w);

    // Flash attention
    dim3 g2(NDIM / 128, BDIM * NHEADS);
    attn_kernel<<<g2, 128, 102400>>>(out);
}